// round 13
// baseline (speedup 1.0000x reference)
#include <cuda_runtime.h>
#include <math.h>

// Fixed problem shapes (B=256, R=512, D=64, N=100000, E=3.2M)
#define RR   512
#define DD   64
#define BB   256
#define NN   100000
#define NBW  3136         // bitmap words: ceil(100000/32)=3125, padded
#define DIN  132          // 2*DD + 4
#define TBL  1024         // hash table slots (load factor <= 0.25)
#define TBLM (TBL - 1)
#define EMPTY_KEY (-1)
#define NCHUNK 16         // gather chunks (64 threads each) in k_fuse
#define EGRID 592         // edge blocks: 4 per SM

// Scratch (device globals; cleared by memset nodes each launch)
__device__ int g_Mq[BB * RR];     // per-representative-b relation counts
__device__ int g_relc[RR];        // global relation histogram

__device__ __forceinline__ unsigned hash_ent(int x) {
    return ((unsigned)x * 2654435761u) >> 16;
}

// ---------------------------------------------------------------- edge scan
// Fast path: SMEM membership bitmap (1 LDS + bit test per endpoint).
// Slow path (rare): bounded SMEM hash probe -> global atomic into g_Mq.
__device__ __forceinline__ void lookup_add(int e, int y,
                                           const int* __restrict__ skeys,
                                           const int* __restrict__ svals) {
    unsigned s = hash_ent(e) & TBLM;
    #pragma unroll 1
    for (int p = 0; p < TBL; p++) {
        int k = skeys[s];
        if (k == e) { atomicAdd(&g_Mq[svals[s] * RR + y], 1); return; }
        if (k == EMPTY_KEY) return;
        s = (s + 1) & TBLM;
    }
}

__device__ __forceinline__ void process_edge(int h, int t, int y,
                                             const unsigned* __restrict__ sbit,
                                             const int* __restrict__ skeys,
                                             const int* __restrict__ svals,
                                             int* __restrict__ shist) {
    atomicAdd(&shist[y], 1);
    bool hh = (sbit[h >> 5] >> (h & 31)) & 1u;
    bool ht = ((sbit[t >> 5] >> (t & 31)) & 1u) && (t != h);  // self-loop once
    if (hh | ht) {                          // rare
        if (hh) lookup_add(h, y, skeys, svals);
        if (ht) lookup_add(t, y, skeys, svals);
    }
}

__global__ __launch_bounds__(256) void k_edges(const int* __restrict__ heads,
                                               const int* __restrict__ tails,
                                               const int* __restrict__ types,
                                               const int* __restrict__ qent,
                                               int B, int E) {
    __shared__ unsigned sbit[NBW];          // 12.25 KB membership bitmap
    __shared__ int skeys[TBL];              // 4 KB
    __shared__ int svals[TBL];              // 4 KB
    __shared__ int shist[RR];               // 2 KB
    int tid = threadIdx.x;
    for (int j = tid; j < NBW; j += 256) sbit[j] = 0u;
    for (int j = tid; j < TBL; j += 256) { skeys[j] = EMPTY_KEY; svals[j] = 0x7FFFFFFF; }
    for (int j = tid; j < RR; j += 256) shist[j] = 0;
    __syncthreads();
    // build bitmap + hash from qent (dedup via min-b); bounded probes
    for (int q = tid; q < B; q += 256) {
        int ent = qent[q];
        atomicOr(&sbit[ent >> 5], 1u << (ent & 31));
        unsigned s = hash_ent(ent) & TBLM;
        #pragma unroll 1
        for (int p = 0; p < TBL; p++) {
            int prev = atomicCAS(&skeys[s], EMPTY_KEY, ent);
            if (prev == EMPTY_KEY || prev == ent) {
                atomicMin(&svals[s], q);    // representative = min b
                break;
            }
            s = (s + 1) & TBLM;
        }
    }
    __syncthreads();

    const int4* h4 = (const int4*)heads;
    const int4* t4 = (const int4*)tails;
    const int4* y4 = (const int4*)types;
    int E4 = E >> 2;
    int gid = blockIdx.x * blockDim.x + tid;
    int stride = gridDim.x * blockDim.x;
    for (int i = gid; i < E4; i += stride) {
        int4 h = h4[i];
        int4 t = t4[i];
        int4 y = y4[i];
        process_edge(h.x, t.x, y.x, sbit, skeys, svals, shist);
        process_edge(h.y, t.y, y.y, sbit, skeys, svals, shist);
        process_edge(h.z, t.z, y.z, sbit, skeys, svals, shist);
        process_edge(h.w, t.w, y.w, sbit, skeys, svals, shist);
    }
    if (blockIdx.x == 0 && tid < (E & 3)) {
        int e = (E4 << 2) + tid;
        process_edge(heads[e], tails[e], types[e], sbit, skeys, svals, shist);
    }
    __syncthreads();
    for (int j = tid; j < RR; j += 256) {
        int v = shist[j];
        if (v) atomicAdd(&g_relc[j], v);
    }
}

// ---------------------------------------------------------------- fused epilogue
// One block of 1024 threads per b: rep scan -> Mq row -> ballot-compact
// nonzeros -> dense branch-free gather (16 chunks x 64 d, 4 accs) ->
// fixed-order reduce -> MLP (W1 split 4 ways).
__global__ __launch_bounds__(1024) void k_fuse(
    const float* __restrict__ rel_emb,   // [B, R, D]
    const int* __restrict__ qrels,
    const int* __restrict__ qent,
    const float* __restrict__ W1, const float* __restrict__ b1,
    const float* __restrict__ W2, const float* __restrict__ b2,
    const float* __restrict__ W3, const float* __restrict__ b3,
    const float* __restrict__ W4, const float* __restrict__ b4,
    float* __restrict__ out, int B, int E, float density) {
    int b = blockIdx.x;
    int tid = threadIdx.x;
    int lane = tid & 31;
    int w = tid >> 5;

    __shared__ float scnt[RR];      // compacted counts
    __shared__ int   sridx[RR];     // compacted relation indices
    __shared__ int   scount[16];
    __shared__ int   soff[16];
    __shared__ float spart[NCHUNK * DD];
    __shared__ float sx[DIN];
    __shared__ float sw[4][DD];
    __shared__ float sh1[DD];
    __shared__ float sh2[32];
    __shared__ float sg[16];
    __shared__ int sdeg, srep, snnz;

    if (tid == 0) { sdeg = 0; srep = 0x7FFFFFFF; }
    __syncthreads();
    // rep = min j with qent[j] == qent[b]  (deterministic, direct scan)
    int myent = qent[b];
    if (tid < B && qent[tid] == myent) atomicMin(&srep, tid);
    __syncthreads();
    int rep = srep;
    int qr = qrels[b];

    // ---- Mq row load + deg + ballot compaction (tid<512, 16 warps)
    if (tid < RR) {
        int c = g_Mq[rep * RR + tid];
        int cs = c;
        #pragma unroll
        for (int o = 16; o; o >>= 1) cs += __shfl_down_sync(0xffffffffu, cs, o);
        if (lane == 0) atomicAdd(&sdeg, cs);     // integer: deterministic
        unsigned bal = __ballot_sync(0xffffffffu, c != 0);
        if (lane == 0) scount[w] = __popc(bal);
        __syncwarp();
        // scatter after offsets are known (below)
        // stash c and bal in registers; need offsets first -> barrier
        // (do scatter post-sync using recomputed mask)
        // store via second phase:
        sridx[tid] = c;   // temp: raw counts parked in sridx
    }
    __syncthreads();
    if (tid == 0) {
        int acc = 0;
        #pragma unroll
        for (int s = 0; s < 16; s++) { soff[s] = acc; acc += scount[s]; }
        snnz = acc;
    }
    __syncthreads();
    if (tid < RR) {
        int c = sridx[tid];                      // parked raw count
        unsigned bal = __ballot_sync(0xffffffffu, c != 0);
        if (c) {
            int p = soff[w] + __popc(bal & ((1u << lane) - 1u));
            scnt[p] = (float)c;
        }
    }
    __syncthreads();
    // rewrite sridx with compacted indices (second pass, same ballot math)
    if (tid < RR) {
        int c = (scnt[0] == scnt[0]) ? 0 : 0;    // no-op; keep structure
        int raw = g_Mq[rep * RR + tid];          // L2-hot reread
        unsigned bal = __ballot_sync(0xffffffffu, raw != 0);
        if (raw) {
            int p = soff[w] + __popc(bal & ((1u << lane) - 1u));
            sridx[p] = tid;
        }
        (void)c;
    }
    __syncthreads();

    int nnz = snnz;
    float deg = (float)sdeg;
    float inv = 1.0f / fmaxf(deg, 1.0f);

    // ---- dense gather: chunk = tid>>6 in [0,16), 4 independent accumulators
    {
        int d = tid & 63;
        int ch = tid >> 6;
        const float* base = rel_emb + (size_t)b * RR * DD + d;
        float a0 = 0.f, a1 = 0.f, a2 = 0.f, a3 = 0.f;
        int i = ch;
        while (i + 3 * NCHUNK < nnz) {
            int r0 = sridx[i];              float w0 = scnt[i];
            int r1 = sridx[i + NCHUNK];     float w1 = scnt[i + NCHUNK];
            int r2 = sridx[i + 2 * NCHUNK]; float w2 = scnt[i + 2 * NCHUNK];
            int r3 = sridx[i + 3 * NCHUNK]; float w3 = scnt[i + 3 * NCHUNK];
            a0 = fmaf(w0, base[(size_t)r0 * DD], a0);
            a1 = fmaf(w1, base[(size_t)r1 * DD], a1);
            a2 = fmaf(w2, base[(size_t)r2 * DD], a2);
            a3 = fmaf(w3, base[(size_t)r3 * DD], a3);
            i += 4 * NCHUNK;
        }
        if (i < nnz) { a0 = fmaf(scnt[i], base[(size_t)sridx[i] * DD], a0); i += NCHUNK; }
        if (i < nnz) { a1 = fmaf(scnt[i], base[(size_t)sridx[i] * DD], a1); i += NCHUNK; }
        if (i < nnz) { a2 = fmaf(scnt[i], base[(size_t)sridx[i] * DD], a2); }
        spart[ch * DD + d] = (a0 + a1) + (a2 + a3);   // fixed order
    }

    if (tid < DD)
        sx[tid] = rel_emb[((size_t)b * RR + qr) * DD + tid];
    __syncthreads();
    if (tid < DD) {
        const float* p = spart + tid;
        float s = 0.f;
        #pragma unroll
        for (int c = 0; c < NCHUNK; c++) s += p[c * DD];   // fixed order
        sx[DD + tid] = s * inv;
    }
    if (tid == 0) {
        float freq = fminf((float)g_relc[qr] / (float)E, 1.0f);
        float degn = fminf(deg / (float)E, 1.0f);
        sx[128] = freq;
        sx[129] = degn;
        sx[130] = freq;
        sx[131] = density;
    }
    __syncthreads();

    // W1: 132 -> 64, input range split across 4 groups of 33, 256 threads
    if (tid < 256) {
        int o = tid & 63;
        int h = tid >> 6;           // 0..3, inputs [h*33, h*33+33)
        int i0 = h * 33;
        float a0 = 0.f, a1 = 0.f, a2 = 0.f, a3 = 0.f;
        const float* wcol = W1 + o;
        #pragma unroll
        for (int i = 0; i < 32; i += 4) {
            a0 = fmaf(sx[i0 + i],     wcol[(i0 + i) * 64],     a0);
            a1 = fmaf(sx[i0 + i + 1], wcol[(i0 + i + 1) * 64], a1);
            a2 = fmaf(sx[i0 + i + 2], wcol[(i0 + i + 2) * 64], a2);
            a3 = fmaf(sx[i0 + i + 3], wcol[(i0 + i + 3) * 64], a3);
        }
        a0 = fmaf(sx[i0 + 32], wcol[(i0 + 32) * 64], a0);
        sw[h][o] = (a0 + a1) + (a2 + a3);
    }
    __syncthreads();
    if (tid < DD)
        sh1[tid] = fmaxf(b1[tid] + (sw[0][tid] + sw[1][tid])
                                 + (sw[2][tid] + sw[3][tid]), 0.0f);
    __syncthreads();
    if (tid < 32) {
        float a0 = b2[tid], a1 = 0.f, a2 = 0.f, a3 = 0.f;
        #pragma unroll
        for (int i = 0; i < 64; i += 4) {
            a0 = fmaf(sh1[i],     W2[i * 32 + tid],       a0);
            a1 = fmaf(sh1[i + 1], W2[(i + 1) * 32 + tid], a1);
            a2 = fmaf(sh1[i + 2], W2[(i + 2) * 32 + tid], a2);
            a3 = fmaf(sh1[i + 3], W2[(i + 3) * 32 + tid], a3);
        }
        sh2[tid] = fmaxf((a0 + a1) + (a2 + a3), 0.0f);
    }
    __syncthreads();
    if (tid < 16) {
        float a0 = b3[tid], a1 = 0.f;
        #pragma unroll
        for (int i = 0; i < 32; i += 2) {
            a0 = fmaf(sh2[i],     W3[i * 16 + tid],       a0);
            a1 = fmaf(sh2[i + 1], W3[(i + 1) * 16 + tid], a1);
        }
        sg[tid] = fmaxf(a0 + a1, 0.0f);
    }
    __syncthreads();
    if (tid == 0) {
        float acc = b4[0];
        #pragma unroll
        for (int i = 0; i < 16; i++) acc = fmaf(sg[i], W4[i], acc);
        out[b] = 1.0f / (1.0f + expf(-acc));
    }
}

// ---------------------------------------------------------------- launch
extern "C" void kernel_launch(void* const* d_in, const int* in_sizes, int n_in,
                              void* d_out, int out_size) {
    const float* rel_emb = (const float*)d_in[0];
    const int*   qrels   = (const int*)d_in[1];
    const int*   qent    = (const int*)d_in[2];
    const int*   eidx    = (const int*)d_in[3];
    const int*   etype   = (const int*)d_in[4];
    const float* W1 = (const float*)d_in[n_in - 8];
    const float* b1 = (const float*)d_in[n_in - 7];
    const float* W2 = (const float*)d_in[n_in - 6];
    const float* b2 = (const float*)d_in[n_in - 5];
    const float* W3 = (const float*)d_in[n_in - 4];
    const float* b3 = (const float*)d_in[n_in - 3];
    const float* W4 = (const float*)d_in[n_in - 2];
    const float* b4 = (const float*)d_in[n_in - 1];

    int B = in_sizes[1];          // 256
    int E = in_sizes[4];          // 3,200,000
    const int* heads = eidx;
    const int* tails = eidx + E;

    double Nd = (double)NN;       // fixed problem
    float density = (float)fmin((double)E / (Nd * Nd), 1.0);

    // clears as graph memset nodes (no init-kernel launch overhead)
    void* pMq = nullptr;
    void* pRc = nullptr;
    cudaGetSymbolAddress(&pMq, g_Mq);
    cudaGetSymbolAddress(&pRc, g_relc);
    cudaMemsetAsync(pMq, 0, BB * RR * sizeof(int));
    cudaMemsetAsync(pRc, 0, RR * sizeof(int));

    k_edges<<<EGRID, 256>>>(heads, tails, etype, qent, B, E);
    k_fuse<<<BB, 1024>>>(rel_emb, qrels, qent,
                         W1, b1, W2, b2, W3, b3, W4, b4,
                         (float*)d_out, B, E, density);
}

// round 14
// speedup vs baseline: 1.1560x; 1.1560x over previous
#include <cuda_runtime.h>
#include <math.h>

// Fixed problem shapes (B=256, R=512, D=64, N=100000, E=3.2M)
#define RR   512
#define DD   64
#define BB   256
#define NN   100000
#define NBW  3136         // bitmap words: ceil(100000/32)=3125, padded
#define DIN  132          // 2*DD + 4
#define TBL  1024         // hash table slots (load factor <= 0.25)
#define TBLM (TBL - 1)
#define EMPTY_KEY (-1)
#define EGRID 592         // edge blocks: 4 per SM

// Combined scratch: [0, BB*RR) = Mq rows, [BB*RR, BB*RR+RR) = relc.
// One symbol -> ONE memset node per launch.
__device__ int g_scratch[BB * RR + RR];

__device__ __forceinline__ unsigned hash_ent(int x) {
    return ((unsigned)x * 2654435761u) >> 16;
}

// ---------------------------------------------------------------- edge scan
// Fast path: SMEM membership bitmap (1 LDS + bit test per endpoint).
// Slow path (rare): bounded SMEM hash probe -> global atomic into Mq.
__device__ __forceinline__ void lookup_add(int e, int y,
                                           const int* __restrict__ skeys,
                                           const int* __restrict__ svals) {
    unsigned s = hash_ent(e) & TBLM;
    #pragma unroll 1
    for (int p = 0; p < TBL; p++) {
        int k = skeys[s];
        if (k == e) { atomicAdd(&g_scratch[svals[s] * RR + y], 1); return; }
        if (k == EMPTY_KEY) return;
        s = (s + 1) & TBLM;
    }
}

__device__ __forceinline__ void process_edge(int h, int t, int y,
                                             const unsigned* __restrict__ sbit,
                                             const int* __restrict__ skeys,
                                             const int* __restrict__ svals,
                                             int* __restrict__ shist) {
    atomicAdd(&shist[y], 1);
    bool hh = (sbit[h >> 5] >> (h & 31)) & 1u;
    bool ht = ((sbit[t >> 5] >> (t & 31)) & 1u) && (t != h);  // self-loop once
    if (hh | ht) {                          // rare
        if (hh) lookup_add(h, y, skeys, svals);
        if (ht) lookup_add(t, y, skeys, svals);
    }
}

__global__ __launch_bounds__(256) void k_edges(const int* __restrict__ heads,
                                               const int* __restrict__ tails,
                                               const int* __restrict__ types,
                                               const int* __restrict__ qent,
                                               int B, int E) {
    __shared__ unsigned sbit[NBW];          // 12.25 KB membership bitmap
    __shared__ int skeys[TBL];              // 4 KB
    __shared__ int svals[TBL];              // 4 KB
    __shared__ int shist[RR];               // 2 KB
    int tid = threadIdx.x;
    for (int j = tid; j < NBW; j += 256) sbit[j] = 0u;
    for (int j = tid; j < TBL; j += 256) { skeys[j] = EMPTY_KEY; svals[j] = 0x7FFFFFFF; }
    for (int j = tid; j < RR; j += 256) shist[j] = 0;
    __syncthreads();
    // build bitmap + hash from qent (dedup via min-b); bounded probes
    for (int q = tid; q < B; q += 256) {
        int ent = qent[q];
        atomicOr(&sbit[ent >> 5], 1u << (ent & 31));
        unsigned s = hash_ent(ent) & TBLM;
        #pragma unroll 1
        for (int p = 0; p < TBL; p++) {
            int prev = atomicCAS(&skeys[s], EMPTY_KEY, ent);
            if (prev == EMPTY_KEY || prev == ent) {
                atomicMin(&svals[s], q);    // representative = min b
                break;
            }
            s = (s + 1) & TBLM;
        }
    }
    __syncthreads();

    const int4* h4 = (const int4*)heads;
    const int4* t4 = (const int4*)tails;
    const int4* y4 = (const int4*)types;
    int E4 = E >> 2;
    int gid = blockIdx.x * blockDim.x + tid;
    int stride = gridDim.x * blockDim.x;
    for (int i = gid; i < E4; i += stride) {
        int4 h = h4[i];
        int4 t = t4[i];
        int4 y = y4[i];
        process_edge(h.x, t.x, y.x, sbit, skeys, svals, shist);
        process_edge(h.y, t.y, y.y, sbit, skeys, svals, shist);
        process_edge(h.z, t.z, y.z, sbit, skeys, svals, shist);
        process_edge(h.w, t.w, y.w, sbit, skeys, svals, shist);
    }
    if (blockIdx.x == 0 && tid < (E & 3)) {
        int e = (E4 << 2) + tid;
        process_edge(heads[e], tails[e], types[e], sbit, skeys, svals, shist);
    }
    __syncthreads();
    int* relc = g_scratch + BB * RR;
    for (int j = tid; j < RR; j += 256) {
        int v = shist[j];
        if (v) atomicAdd(&relc[j], v);
    }
}

// ---------------------------------------------------------------- fused epilogue
// 256 threads per b (many blocks/SM -> cross-block latency overlap):
// rep scan -> Mq row (both halves in regs) -> ballot compaction -> dense
// 4-chunk x 4-acc gather -> fixed-order reduce -> MLP.
__global__ __launch_bounds__(256) void k_fuse(
    const float* __restrict__ rel_emb,   // [B, R, D]
    const int* __restrict__ qrels,
    const int* __restrict__ qent,
    const float* __restrict__ W1, const float* __restrict__ b1,
    const float* __restrict__ W2, const float* __restrict__ b2,
    const float* __restrict__ W3, const float* __restrict__ b3,
    const float* __restrict__ W4, const float* __restrict__ b4,
    float* __restrict__ out, int B, int E, float density) {
    int b = blockIdx.x;
    int tid = threadIdx.x;
    int lane = tid & 31;
    int w = tid >> 5;               // 8 warps

    __shared__ float scnt[RR];      // compacted counts
    __shared__ int   sridx[RR];     // compacted relation indices
    __shared__ int   scount[16];
    __shared__ int   soff[16];
    __shared__ float spart[4 * DD];
    __shared__ float sx[DIN];
    __shared__ float sw[4][DD];
    __shared__ float sh1[DD];
    __shared__ float sh2[32];
    __shared__ float sg[16];
    __shared__ int sdeg, srep, snnz;

    if (tid == 0) { sdeg = 0; srep = 0x7FFFFFFF; }
    __syncthreads();
    // rep = min j with qent[j] == qent[b]  (deterministic, direct scan)
    int myent = qent[b];
    if (tid < B && qent[tid] == myent) atomicMin(&srep, tid);
    __syncthreads();
    int rep = srep;
    int qr = qrels[b];

    // ---- Mq row (two counts per thread) + deg + ballot compaction
    int c0 = g_scratch[rep * RR + tid];
    int c1 = g_scratch[rep * RR + 256 + tid];
    int ds = c0 + c1;
    #pragma unroll
    for (int o = 16; o; o >>= 1) ds += __shfl_down_sync(0xffffffffu, ds, o);
    if (lane == 0) atomicAdd(&sdeg, ds);    // integer: deterministic
    unsigned bal0 = __ballot_sync(0xffffffffu, c0 != 0);
    unsigned bal1 = __ballot_sync(0xffffffffu, c1 != 0);
    if (lane == 0) { scount[w] = __popc(bal0); scount[8 + w] = __popc(bal1); }
    __syncthreads();
    if (tid == 0) {
        int acc = 0;
        #pragma unroll
        for (int s = 0; s < 16; s++) { soff[s] = acc; acc += scount[s]; }
        snnz = acc;
    }
    __syncthreads();
    unsigned ltm = (1u << lane) - 1u;
    if (c0) {
        int p = soff[w] + __popc(bal0 & ltm);
        sridx[p] = tid;        scnt[p] = (float)c0;
    }
    if (c1) {
        int p = soff[8 + w] + __popc(bal1 & ltm);
        sridx[p] = 256 + tid;  scnt[p] = (float)c1;
    }
    __syncthreads();

    int nnz = snnz;
    float deg = (float)sdeg;
    float inv = 1.0f / fmaxf(deg, 1.0f);

    // ---- dense gather: 4 chunks (tid>>6) x 64 d, 4 independent accumulators
    {
        int d = tid & 63;
        int j = tid >> 6;
        const float* base = rel_emb + (size_t)b * RR * DD + d;
        float a0 = 0.f, a1 = 0.f, a2 = 0.f, a3 = 0.f;
        int i = j;
        while (i + 12 < nnz) {
            int r0 = sridx[i];      float w0 = scnt[i];
            int r1 = sridx[i + 4];  float w1 = scnt[i + 4];
            int r2 = sridx[i + 8];  float w2 = scnt[i + 8];
            int r3 = sridx[i + 12]; float w3 = scnt[i + 12];
            a0 = fmaf(w0, base[(size_t)r0 * DD], a0);
            a1 = fmaf(w1, base[(size_t)r1 * DD], a1);
            a2 = fmaf(w2, base[(size_t)r2 * DD], a2);
            a3 = fmaf(w3, base[(size_t)r3 * DD], a3);
            i += 16;
        }
        if (i < nnz) { a0 = fmaf(scnt[i], base[(size_t)sridx[i] * DD], a0); i += 4; }
        if (i < nnz) { a1 = fmaf(scnt[i], base[(size_t)sridx[i] * DD], a1); i += 4; }
        if (i < nnz) { a2 = fmaf(scnt[i], base[(size_t)sridx[i] * DD], a2); }
        spart[j * DD + d] = (a0 + a1) + (a2 + a3);  // fixed order
    }

    if (tid < DD)
        sx[tid] = rel_emb[((size_t)b * RR + qr) * DD + tid];
    __syncthreads();
    if (tid < DD) {
        float s = (spart[tid] + spart[64 + tid])
                + (spart[128 + tid] + spart[192 + tid]);   // fixed order
        sx[DD + tid] = s * inv;
    }
    if (tid == 0) {
        const int* relc = g_scratch + BB * RR;
        float freq = fminf((float)relc[qr] / (float)E, 1.0f);
        float degn = fminf(deg / (float)E, 1.0f);
        sx[128] = freq;
        sx[129] = degn;
        sx[130] = freq;
        sx[131] = density;
    }
    __syncthreads();

    // W1: 132 -> 64, input range split across 4 groups of 33, 256 threads
    {
        int o = tid & 63;
        int h = tid >> 6;           // 0..3, inputs [h*33, h*33+33)
        int i0 = h * 33;
        float a0 = 0.f, a1 = 0.f, a2 = 0.f, a3 = 0.f;
        const float* wcol = W1 + o;
        #pragma unroll
        for (int i = 0; i < 32; i += 4) {
            a0 = fmaf(sx[i0 + i],     wcol[(i0 + i) * 64],     a0);
            a1 = fmaf(sx[i0 + i + 1], wcol[(i0 + i + 1) * 64], a1);
            a2 = fmaf(sx[i0 + i + 2], wcol[(i0 + i + 2) * 64], a2);
            a3 = fmaf(sx[i0 + i + 3], wcol[(i0 + i + 3) * 64], a3);
        }
        a0 = fmaf(sx[i0 + 32], wcol[(i0 + 32) * 64], a0);
        sw[h][o] = (a0 + a1) + (a2 + a3);
    }
    __syncthreads();
    if (tid < DD)
        sh1[tid] = fmaxf(b1[tid] + (sw[0][tid] + sw[1][tid])
                                 + (sw[2][tid] + sw[3][tid]), 0.0f);
    __syncthreads();
    if (tid < 32) {
        float a0 = b2[tid], a1 = 0.f, a2 = 0.f, a3 = 0.f;
        #pragma unroll
        for (int i = 0; i < 64; i += 4) {
            a0 = fmaf(sh1[i],     W2[i * 32 + tid],       a0);
            a1 = fmaf(sh1[i + 1], W2[(i + 1) * 32 + tid], a1);
            a2 = fmaf(sh1[i + 2], W2[(i + 2) * 32 + tid], a2);
            a3 = fmaf(sh1[i + 3], W2[(i + 3) * 32 + tid], a3);
        }
        sh2[tid] = fmaxf((a0 + a1) + (a2 + a3), 0.0f);
    }
    __syncthreads();
    if (tid < 16) {
        float a0 = b3[tid], a1 = 0.f;
        #pragma unroll
        for (int i = 0; i < 32; i += 2) {
            a0 = fmaf(sh2[i],     W3[i * 16 + tid],       a0);
            a1 = fmaf(sh2[i + 1], W3[(i + 1) * 16 + tid], a1);
        }
        sg[tid] = fmaxf(a0 + a1, 0.0f);
    }
    __syncthreads();
    if (tid == 0) {
        float acc = b4[0];
        #pragma unroll
        for (int i = 0; i < 16; i++) acc = fmaf(sg[i], W4[i], acc);
        out[b] = 1.0f / (1.0f + expf(-acc));
    }
}

// ---------------------------------------------------------------- launch
extern "C" void kernel_launch(void* const* d_in, const int* in_sizes, int n_in,
                              void* d_out, int out_size) {
    const float* rel_emb = (const float*)d_in[0];
    const int*   qrels   = (const int*)d_in[1];
    const int*   qent    = (const int*)d_in[2];
    const int*   eidx    = (const int*)d_in[3];
    const int*   etype   = (const int*)d_in[4];
    const float* W1 = (const float*)d_in[n_in - 8];
    const float* b1 = (const float*)d_in[n_in - 7];
    const float* W2 = (const float*)d_in[n_in - 6];
    const float* b2 = (const float*)d_in[n_in - 5];
    const float* W3 = (const float*)d_in[n_in - 4];
    const float* b3 = (const float*)d_in[n_in - 3];
    const float* W4 = (const float*)d_in[n_in - 2];
    const float* b4 = (const float*)d_in[n_in - 1];

    int B = in_sizes[1];          // 256
    int E = in_sizes[4];          // 3,200,000
    const int* heads = eidx;
    const int* tails = eidx + E;

    double Nd = (double)NN;       // fixed problem
    float density = (float)fmin((double)E / (Nd * Nd), 1.0);

    // single clear node for all scratch
    void* pS = nullptr;
    cudaGetSymbolAddress(&pS, g_scratch);
    cudaMemsetAsync(pS, 0, (BB * RR + RR) * sizeof(int));

    k_edges<<<EGRID, 256>>>(heads, tails, etype, qent, B, E);
    k_fuse<<<BB, 256>>>(rel_emb, qrels, qent,
                        W1, b1, W2, b2, W3, b3, W4, b4,
                        (float*)d_out, B, E, density);
}